// round 2
// baseline (speedup 1.0000x reference)
#include <cuda_runtime.h>

// Fused MoE: gate softmax + per-expert (x@Ws + ctx@Wc + bs -> relu -> @Wf + bf)
// + gate-weighted reduction, all in one kernel.
// Round 1: fp32 FFMA baseline. d_out layout assumed: [final_output (B*128) | gate (B*4)].

#define THREADS 256
#define ROWS    64      // rows per block
#define Hdim    256
#define Cdim    64
#define K1      320     // H + C
#define H2dim   128
#define Odim    128
#define Edim    4
#define KT      64      // k-tile for weight staging

__device__ __forceinline__ void fma4(float4& a, float x, const float4 w) {
    a.x = fmaf(x, w.x, a.x);
    a.y = fmaf(x, w.y, a.y);
    a.z = fmaf(x, w.z, a.z);
    a.w = fmaf(x, w.w, a.w);
}

__global__ __launch_bounds__(THREADS, 1)
void fused_moe_kernel(const float* __restrict__ hidden,
                      const float* __restrict__ context,
                      const float* __restrict__ Wg,
                      const float* __restrict__ bg,
                      const float* __restrict__ Ws,
                      const float* __restrict__ Wc,
                      const float* __restrict__ bs,
                      const float* __restrict__ Wf,
                      const float* __restrict__ bf,
                      float* __restrict__ out_final,
                      float* __restrict__ out_gate)
{
    extern __shared__ float smem[];
    float* xs = smem;                    // ROWS * K1      = 20480 floats
    float* ws = xs + ROWS * K1;          // KT * 128       = 8192 floats (weight k-tile)
    float* hs = ws + KT * H2dim;         // ROWS * H2      = 8192 floats
    float* gs = hs + ROWS * H2dim;       // ROWS * E       = 256 floats

    const int tid = threadIdx.x;
    const int row_base = blockIdx.x * ROWS;
    const int tx   = tid & 31;           // 32 col-groups
    const int ty   = tid >> 5;           // 8 row-groups
    const int col0 = tx * 4;             // 4 cols per thread
    const int row0 = ty * 8;             // 8 rows per thread

    // ---- stage x = [hidden | context] into smem (row stride K1) ----
    {
        const float4* h4 = reinterpret_cast<const float4*>(hidden + (size_t)row_base * Hdim);
        #pragma unroll
        for (int i = tid; i < ROWS * Hdim / 4; i += THREADS) {
            int r = i / (Hdim / 4);
            int c = i % (Hdim / 4);
            *reinterpret_cast<float4*>(&xs[r * K1 + c * 4]) = h4[r * (Hdim / 4) + c];
        }
        const float4* c4 = reinterpret_cast<const float4*>(context + (size_t)row_base * Cdim);
        #pragma unroll
        for (int i = tid; i < ROWS * Cdim / 4; i += THREADS) {
            int r = i / (Cdim / 4);
            int c = i % (Cdim / 4);
            *reinterpret_cast<float4*>(&xs[r * K1 + Hdim + c * 4]) = c4[r * (Cdim / 4) + c];
        }
    }
    // ---- stage Wg [256,4] into ws ----
    for (int i = tid; i < Hdim * Edim; i += THREADS) ws[i] = Wg[i];
    __syncthreads();

    // ---- gate logits: one (row, expert) pair per thread ----
    {
        const int grow = tid >> 2;
        const int ge   = tid & 3;
        float logit = bg[ge];
        const float* xr = &xs[grow * K1];
        #pragma unroll 8
        for (int k = 0; k < Hdim; k++)
            logit = fmaf(xr[k], ws[k * Edim + ge], logit);
        gs[grow * Edim + ge] = logit;
    }
    __syncthreads();
    // ---- softmax (one thread per row) + write gate output ----
    if (tid < ROWS) {
        float l0 = gs[tid * 4 + 0], l1 = gs[tid * 4 + 1];
        float l2 = gs[tid * 4 + 2], l3 = gs[tid * 4 + 3];
        float m  = fmaxf(fmaxf(l0, l1), fmaxf(l2, l3));
        float e0 = __expf(l0 - m), e1 = __expf(l1 - m);
        float e2 = __expf(l2 - m), e3 = __expf(l3 - m);
        float inv = 1.0f / (e0 + e1 + e2 + e3);
        e0 *= inv; e1 *= inv; e2 *= inv; e3 *= inv;
        gs[tid * 4 + 0] = e0; gs[tid * 4 + 1] = e1;
        gs[tid * 4 + 2] = e2; gs[tid * 4 + 3] = e3;
        *reinterpret_cast<float4*>(&out_gate[(size_t)(row_base + tid) * 4]) =
            make_float4(e0, e1, e2, e3);
    }
    __syncthreads();

    // ---- expert loop ----
    float4 oacc[8];
    #pragma unroll
    for (int i = 0; i < 8; i++) oacc[i] = make_float4(0.f, 0.f, 0.f, 0.f);

    for (int e = 0; e < Edim; e++) {
        // ===== GEMM1: h = x @ [Ws[e]; Wc[e]] + bs[e] =====
        float4 acc[8];
        {
            float4 b = *reinterpret_cast<const float4*>(&bs[e * H2dim + col0]);
            #pragma unroll
            for (int i = 0; i < 8; i++) acc[i] = b;
        }
        #pragma unroll 1
        for (int kt = 0; kt < 5; kt++) {   // 4 tiles from Ws, 1 from Wc
            const float* src = (kt < 4)
                ? (Ws + ((size_t)e * Hdim + kt * KT) * H2dim)
                : (Wc + (size_t)e * Cdim * H2dim);
            __syncthreads();
            #pragma unroll
            for (int i = tid; i < KT * H2dim / 4; i += THREADS)
                reinterpret_cast<float4*>(ws)[i] = reinterpret_cast<const float4*>(src)[i];
            __syncthreads();
            const int kg0 = kt * KT;
            #pragma unroll 2
            for (int kk = 0; kk < KT; kk += 4) {
                const float4 w0 = *reinterpret_cast<const float4*>(&ws[(kk + 0) * H2dim + col0]);
                const float4 w1 = *reinterpret_cast<const float4*>(&ws[(kk + 1) * H2dim + col0]);
                const float4 w2 = *reinterpret_cast<const float4*>(&ws[(kk + 2) * H2dim + col0]);
                const float4 w3 = *reinterpret_cast<const float4*>(&ws[(kk + 3) * H2dim + col0]);
                #pragma unroll
                for (int i = 0; i < 8; i++) {
                    const float4 xv = *reinterpret_cast<const float4*>(&xs[(row0 + i) * K1 + kg0 + kk]);
                    fma4(acc[i], xv.x, w0);
                    fma4(acc[i], xv.y, w1);
                    fma4(acc[i], xv.z, w2);
                    fma4(acc[i], xv.w, w3);
                }
            }
        }
        // relu -> hs
        __syncthreads();
        #pragma unroll
        for (int i = 0; i < 8; i++) {
            float4 v = acc[i];
            v.x = fmaxf(v.x, 0.f); v.y = fmaxf(v.y, 0.f);
            v.z = fmaxf(v.z, 0.f); v.w = fmaxf(v.w, 0.f);
            *reinterpret_cast<float4*>(&hs[(row0 + i) * H2dim + col0]) = v;
        }

        // ===== GEMM2: o_e = relu(h) @ Wf[e] + bf[e] =====
        float4 acc2[8];
        {
            float4 b = *reinterpret_cast<const float4*>(&bf[e * Odim + col0]);
            #pragma unroll
            for (int i = 0; i < 8; i++) acc2[i] = b;
        }
        #pragma unroll 1
        for (int kt = 0; kt < 2; kt++) {
            const float* src = Wf + ((size_t)e * H2dim + kt * KT) * Odim;
            __syncthreads();
            #pragma unroll
            for (int i = tid; i < KT * Odim / 4; i += THREADS)
                reinterpret_cast<float4*>(ws)[i] = reinterpret_cast<const float4*>(src)[i];
            __syncthreads();
            const int kg0 = kt * KT;
            #pragma unroll 2
            for (int kk = 0; kk < KT; kk += 4) {
                const float4 w0 = *reinterpret_cast<const float4*>(&ws[(kk + 0) * Odim + col0]);
                const float4 w1 = *reinterpret_cast<const float4*>(&ws[(kk + 1) * Odim + col0]);
                const float4 w2 = *reinterpret_cast<const float4*>(&ws[(kk + 2) * Odim + col0]);
                const float4 w3 = *reinterpret_cast<const float4*>(&ws[(kk + 3) * Odim + col0]);
                #pragma unroll
                for (int i = 0; i < 8; i++) {
                    const float4 xv = *reinterpret_cast<const float4*>(&hs[(row0 + i) * H2dim + kg0 + kk]);
                    fma4(acc2[i], xv.x, w0);
                    fma4(acc2[i], xv.y, w1);
                    fma4(acc2[i], xv.z, w2);
                    fma4(acc2[i], xv.w, w3);
                }
            }
        }
        // gate-weighted accumulate
        #pragma unroll
        for (int i = 0; i < 8; i++) {
            const float g = gs[(row0 + i) * Edim + e];
            oacc[i].x = fmaf(g, acc2[i].x, oacc[i].x);
            oacc[i].y = fmaf(g, acc2[i].y, oacc[i].y);
            oacc[i].z = fmaf(g, acc2[i].z, oacc[i].z);
            oacc[i].w = fmaf(g, acc2[i].w, oacc[i].w);
        }
    }

    // ---- write final output ----
    #pragma unroll
    for (int i = 0; i < 8; i++)
        *reinterpret_cast<float4*>(&out_final[(size_t)(row_base + row0 + i) * Odim + col0]) = oacc[i];
}

extern "C" void kernel_launch(void* const* d_in, const int* in_sizes, int n_in,
                              void* d_out, int out_size) {
    const float* hidden  = (const float*)d_in[0];
    const float* context = (const float*)d_in[1];
    const float* Wg      = (const float*)d_in[2];
    const float* bg      = (const float*)d_in[3];
    const float* Ws      = (const float*)d_in[4];
    const float* Wc      = (const float*)d_in[5];
    const float* bs      = (const float*)d_in[6];
    const float* Wf      = (const float*)d_in[7];
    const float* bf      = (const float*)d_in[8];

    const int B = in_sizes[0] / Hdim;    // 131072

    float* out_final = (float*)d_out;
    float* out_gate  = (float*)d_out + (size_t)B * Odim;

    const int smem_bytes = (ROWS * K1 + KT * H2dim + ROWS * H2dim + ROWS * Edim) * (int)sizeof(float);
    cudaFuncSetAttribute(fused_moe_kernel, cudaFuncAttributeMaxDynamicSharedMemorySize, smem_bytes);

    fused_moe_kernel<<<B / ROWS, THREADS, smem_bytes>>>(
        hidden, context, Wg, bg, Ws, Wc, bs, Wf, bf, out_final, out_gate);
}